// round 1
// baseline (speedup 1.0000x reference)
#include <cuda_runtime.h>
#include <cuda_bf16.h>

// Problem: B=16, C=64, H=128, W=128
//   masked_l1[b,c] = sum_hw |pre-gt| * mask
//   nonzero[b,c]   = count(mask != 0)
//   loss = sum_bc( masked_l1 / max(nonzero,1) ) / B
//
// Strategy: 1 CTA per (b,c) pair (1024 CTAs), 256 threads.
// Each thread: 16 float4 loads per tensor (fully coalesced, 48 independent
// 16B loads in flight -> DRAM latency hidden). Block reduce, one float
// atomicAdd per CTA into the scalar output.

#define BATCH   16
#define CHAN    64
#define HW      (128 * 128)          // 16384 elements per (b,c)
#define NBC     (BATCH * CHAN)       // 1024
#define THREADS 256
#define V4_PER_THREAD (HW / 4 / THREADS)   // 16

__global__ void zero_out_kernel(float* out) {
    if (threadIdx.x == 0) out[0] = 0.0f;
}

__global__ __launch_bounds__(THREADS, 8)
void l1loss_kernel(const float4* __restrict__ pre,
                   const float4* __restrict__ gt,
                   const float4* __restrict__ mask,
                   float* __restrict__ out) {
    const int bc = blockIdx.x;                       // 0..1023
    const long base = (long)bc * (HW / 4);           // float4 index of row start

    float s   = 0.0f;   // masked L1 partial
    float cnt = 0.0f;   // nonzero count partial

    #pragma unroll
    for (int i = 0; i < V4_PER_THREAD; i++) {
        const long idx = base + threadIdx.x + (long)i * THREADS;
        const float4 p = __ldg(&pre[idx]);
        const float4 g = __ldg(&gt[idx]);
        const float4 m = __ldg(&mask[idx]);
        s += fabsf(p.x - g.x) * m.x;
        s += fabsf(p.y - g.y) * m.y;
        s += fabsf(p.z - g.z) * m.z;
        s += fabsf(p.w - g.w) * m.w;
        cnt += (m.x != 0.0f) ? 1.0f : 0.0f;
        cnt += (m.y != 0.0f) ? 1.0f : 0.0f;
        cnt += (m.z != 0.0f) ? 1.0f : 0.0f;
        cnt += (m.w != 0.0f) ? 1.0f : 0.0f;
    }

    // Warp reduce (both accumulators)
    #pragma unroll
    for (int off = 16; off > 0; off >>= 1) {
        s   += __shfl_down_sync(0xFFFFFFFFu, s,   off);
        cnt += __shfl_down_sync(0xFFFFFFFFu, cnt, off);
    }

    __shared__ float sh_s[THREADS / 32];
    __shared__ float sh_c[THREADS / 32];
    const int lane = threadIdx.x & 31;
    const int wid  = threadIdx.x >> 5;
    if (lane == 0) { sh_s[wid] = s; sh_c[wid] = cnt; }
    __syncthreads();

    if (wid == 0) {
        s   = (lane < THREADS / 32) ? sh_s[lane] : 0.0f;
        cnt = (lane < THREADS / 32) ? sh_c[lane] : 0.0f;
        #pragma unroll
        for (int off = 4; off > 0; off >>= 1) {
            s   += __shfl_down_sync(0xFFFFFFFFu, s,   off);
            cnt += __shfl_down_sync(0xFFFFFFFFu, cnt, off);
        }
        if (lane == 0) {
            const float q = s / fmaxf(cnt, 1.0f) * (1.0f / (float)BATCH);
            atomicAdd(out, q);
        }
    }
}

extern "C" void kernel_launch(void* const* d_in, const int* in_sizes, int n_in,
                              void* d_out, int out_size) {
    const float4* pre  = (const float4*)d_in[0];
    const float4* gt   = (const float4*)d_in[1];
    const float4* mask = (const float4*)d_in[2];
    float* out = (float*)d_out;

    zero_out_kernel<<<1, 32>>>(out);
    l1loss_kernel<<<NBC, THREADS>>>(pre, gt, mask, out);
}